// round 7
// baseline (speedup 1.0000x reference)
#include <cuda_runtime.h>
#include <math.h>

#define BMAX   4
#define NN     4096
#define DDIM   1024
#define MSPLIT 256
#define MCHUNK (NN / MSPLIT)    // 16
#define EPSV   1e-6f
#define ROWS_PER_BLOCK 16

// Scratch (device globals: no allocation allowed)
__device__ float g_part[BMAX][MSPLIT][3][DDIM]; // partial H0/Hc/Hs (12 MB)
__device__ float g_csp[BMAX][MSPLIT][2];        // partial sum cos / sum sin
__device__ float g_H[BMAX][3][DDIM];            // reduced H0/Hc/Hs
__device__ float g_CS[BMAX][2];                 // final sum cos, sum sin

// ---------------------------------------------------------------------------
// Kernel 1: partial reductions of H0/Hc/Hs over 16-row m-chunks.
// grid = (MSPLIT, B) = 1024 blocks, 256 threads, thread owns 4 consecutive d.
// Each block computes sincos for its own 16 rows (16 threads, once).
// ---------------------------------------------------------------------------
__global__ void __launch_bounds__(256)
kernel_part(const float* __restrict__ hidden,
            const float* __restrict__ phases) {
    __shared__ float smc[MCHUNK], sms[MCHUNK];
    const int b  = blockIdx.y;
    const int ms = blockIdx.x;
    const int m0 = ms * MCHUNK;
    const int t  = threadIdx.x;

    if (t < MCHUNK) {
        float p = phases[b * NN + m0 + t];
        float s, c;
        sincosf(p, &s, &c);
        smc[t] = c;
        sms[t] = s;
        // reduce the 16 trig values -> per-block partial C/S
        float rc = c, rs = s;
#pragma unroll
        for (int off = 8; off > 0; off >>= 1) {
            rc += __shfl_xor_sync(0x0000ffffu, rc, off, 16);
            rs += __shfl_xor_sync(0x0000ffffu, rs, off, 16);
        }
        if (t == 0) { g_csp[b][ms][0] = rc; g_csp[b][ms][1] = rs; }
    }
    __syncthreads();

    const float4* hp = (const float4*)(hidden + ((size_t)b * NN + m0) * DDIM) + t;
    float4 a0 = make_float4(0.f, 0.f, 0.f, 0.f);
    float4 ac = a0, as = a0;

#pragma unroll 8
    for (int m = 0; m < MCHUNK; ++m) {
        float4 h = hp[(size_t)m * (DDIM / 4)];
        float c = smc[m], s = sms[m];
        a0.x += h.x;               a0.y += h.y;
        a0.z += h.z;               a0.w += h.w;
        ac.x = fmaf(c, h.x, ac.x); ac.y = fmaf(c, h.y, ac.y);
        ac.z = fmaf(c, h.z, ac.z); ac.w = fmaf(c, h.w, ac.w);
        as.x = fmaf(s, h.x, as.x); as.y = fmaf(s, h.y, as.y);
        as.z = fmaf(s, h.z, as.z); as.w = fmaf(s, h.w, as.w);
    }
    ((float4*)g_part[b][ms][0])[t] = a0;
    ((float4*)g_part[b][ms][1])[t] = ac;
    ((float4*)g_part[b][ms][2])[t] = as;
}

// ---------------------------------------------------------------------------
// Kernel 2: fold MSPLIT partials -> g_H; one block also folds C/S.
// grid = (12, B) = 48 blocks, 64 threads; bx = comp*4 + quarter.
// Each thread folds one float4 of its d-quarter over all MSPLIT chunks.
// ---------------------------------------------------------------------------
__global__ void __launch_bounds__(64)
kernel_reduce() {
    const int comp = blockIdx.x >> 2;          // 0..2
    const int q    = blockIdx.x & 3;           // d-quarter
    const int b    = blockIdx.y;
    const int t    = threadIdx.x;
    const int e    = q * 64 + t;               // float4 index within DDIM/4=256

    if (blockIdx.x == 0 && t < 64) {
        // fold 256 partial C and 256 partial S with 64 threads:
        // t<32 -> C lanes, t>=32 -> S lanes (each lane folds 8 chunks)
        int which = t >> 5;
        int lane  = t & 31;
        float v = 0.f;
#pragma unroll
        for (int i = 0; i < MSPLIT / 32; ++i)
            v += g_csp[b][lane + i * 32][which];
#pragma unroll
        for (int off = 16; off > 0; off >>= 1)
            v += __shfl_xor_sync(0xffffffffu, v, off, 32);
        if (lane == 0) g_CS[b][which] = v;
    }

    float4 acc = make_float4(0.f, 0.f, 0.f, 0.f);
#pragma unroll 8
    for (int ms = 0; ms < MSPLIT; ++ms) {
        float4 v = ((const float4*)g_part[b][ms][comp])[e];
        acc.x += v.x; acc.y += v.y; acc.z += v.z; acc.w += v.w;
    }
    ((float4*)g_H[b][comp])[e] = acc;
}

// ---------------------------------------------------------------------------
// Kernel 3: output pass — per-block row trig+division (16 threads, once),
// then pure FMA/float4 streaming. hidden reads are L2-hot from kernel_part.
// grid = (NN/ROWS_PER_BLOCK, B) = 1024 blocks, 256 threads.
// ---------------------------------------------------------------------------
__global__ void __launch_bounds__(256)
kernel_out(const float* __restrict__ hidden,
           const float* __restrict__ phases,
           const float* __restrict__ alpha_p,
           float* __restrict__ out) {
    __shared__ float scn[ROWS_PER_BLOCK], ssn[ROWS_PER_BLOCK], scf[ROWS_PER_BLOCK];
    const int b  = blockIdx.y;
    const int n0 = blockIdx.x * ROWS_PER_BLOCK;
    const int t  = threadIdx.x;

    const float a    = fminf(fmaxf(alpha_p[0], 0.f), 1.f);
    const float beta = 1.f - a;

    if (t < ROWS_PER_BLOCK) {
        float p = phases[b * NN + n0 + t];
        float sn, cn;
        sincosf(p, &sn, &cn);
        float C = g_CS[b][0], S = g_CS[b][1];
        float den = fmaxf(0.5f * ((float)NN + fmaf(cn, C, sn * S)), EPSV);
        scn[t] = cn;
        ssn[t] = sn;
        scf[t] = a * 0.5f / den;
    }
    __syncthreads();

    // per-thread slice of the H vectors (L2-broadcast across blocks)
    const float4 H0 = ((const float4*)g_H[b][0])[t];
    const float4 Hc = ((const float4*)g_H[b][1])[t];
    const float4 Hs = ((const float4*)g_H[b][2])[t];

    const float4* hv = (const float4*)(hidden + ((size_t)b * NN + n0) * DDIM) + t;
    float4*       ov = (float4*)(out + ((size_t)b * NN + n0) * DDIM) + t;

#pragma unroll 8
    for (int r = 0; r < ROWS_PER_BLOCK; ++r) {
        float cn = scn[r];
        float sn = ssn[r];
        float cf = scf[r];

        float4 h = hv[(size_t)r * (DDIM / 4)];
        float4 o;
        o.x = fmaf(cf, fmaf(sn, Hs.x, fmaf(cn, Hc.x, H0.x)), beta * h.x);
        o.y = fmaf(cf, fmaf(sn, Hs.y, fmaf(cn, Hc.y, H0.y)), beta * h.y);
        o.z = fmaf(cf, fmaf(sn, Hs.z, fmaf(cn, Hc.z, H0.z)), beta * h.z);
        o.w = fmaf(cf, fmaf(sn, Hs.w, fmaf(cn, Hc.w, H0.w)), beta * h.w);
        ov[(size_t)r * (DDIM / 4)] = o;
    }
}

// ---------------------------------------------------------------------------
// Launch — exactly 3 kernels.
// ---------------------------------------------------------------------------
extern "C" void kernel_launch(void* const* d_in, const int* in_sizes, int n_in,
                              void* d_out, int out_size) {
    const float* hidden = (const float*)d_in[0];
    const float* phases = (const float*)d_in[1];
    const float* alpha  = (const float*)d_in[2];
    float* out = (float*)d_out;

    const int B = in_sizes[1] / NN;

    kernel_part<<<dim3(MSPLIT, B), 256>>>(hidden, phases);
    kernel_reduce<<<dim3(12, B), 64>>>();
    kernel_out<<<dim3(NN / ROWS_PER_BLOCK, B), 256>>>(hidden, phases, alpha, out);
}

// round 8
// speedup vs baseline: 1.4198x; 1.4198x over previous
#include <cuda_runtime.h>
#include <math.h>

#define BMAX   4
#define NN     4096
#define DDIM   1024
#define MSPLIT 128
#define MCHUNK (NN / MSPLIT)    // 32
#define EPSV   1e-6f
#define ROWS_PER_BLOCK 32
#define BATCH  8                 // loads staged per inner iteration

// Scratch (device globals: no allocation allowed)
__device__ float g_part[BMAX][MSPLIT][3][DDIM]; // partial H0/Hc/Hs (6 MB)
__device__ float g_csp[BMAX][MSPLIT][2];        // partial sum cos / sum sin
__device__ float g_H[BMAX][3][DDIM];            // reduced H0/Hc/Hs
__device__ float g_CS[BMAX][2];                 // final sum cos, sum sin

// ---------------------------------------------------------------------------
// Kernel 1: partial reductions of H0/Hc/Hs over 32-row m-chunks.
// grid = (MSPLIT, B) = 512 blocks, 256 threads, thread owns 4 consecutive d.
// Inner loop stages BATCH float4 loads before any FMA (MLP = 8).
// ---------------------------------------------------------------------------
__global__ void __launch_bounds__(256, 4)
kernel_part(const float* __restrict__ hidden,
            const float* __restrict__ phases) {
    __shared__ float smc[MCHUNK], sms[MCHUNK];
    const int b  = blockIdx.y;
    const int ms = blockIdx.x;
    const int m0 = ms * MCHUNK;
    const int t  = threadIdx.x;

    if (t < MCHUNK) {
        float p = phases[b * NN + m0 + t];
        float s, c;
        sincosf(p, &s, &c);
        smc[t] = c;
        sms[t] = s;
        float rc = c, rs = s;
#pragma unroll
        for (int off = 16; off > 0; off >>= 1) {
            rc += __shfl_xor_sync(0xffffffffu, rc, off);
            rs += __shfl_xor_sync(0xffffffffu, rs, off);
        }
        if (t == 0) { g_csp[b][ms][0] = rc; g_csp[b][ms][1] = rs; }
    }
    __syncthreads();

    const float4* hp = (const float4*)(hidden + ((size_t)b * NN + m0) * DDIM) + t;
    float4 a0 = make_float4(0.f, 0.f, 0.f, 0.f);
    float4 ac = a0, as = a0;

    float4 buf[BATCH];
#pragma unroll
    for (int mm = 0; mm < MCHUNK; mm += BATCH) {
#pragma unroll
        for (int i = 0; i < BATCH; ++i)
            buf[i] = hp[(size_t)(mm + i) * (DDIM / 4)];
#pragma unroll
        for (int i = 0; i < BATCH; ++i) {
            float4 h = buf[i];
            float c = smc[mm + i], s = sms[mm + i];
            a0.x += h.x;               a0.y += h.y;
            a0.z += h.z;               a0.w += h.w;
            ac.x = fmaf(c, h.x, ac.x); ac.y = fmaf(c, h.y, ac.y);
            ac.z = fmaf(c, h.z, ac.z); ac.w = fmaf(c, h.w, ac.w);
            as.x = fmaf(s, h.x, as.x); as.y = fmaf(s, h.y, as.y);
            as.z = fmaf(s, h.z, as.z); as.w = fmaf(s, h.w, as.w);
        }
    }
    ((float4*)g_part[b][ms][0])[t] = a0;
    ((float4*)g_part[b][ms][1])[t] = ac;
    ((float4*)g_part[b][ms][2])[t] = as;
}

// ---------------------------------------------------------------------------
// Kernel 2: fold MSPLIT partials -> g_H; block 0 also folds C/S.
// grid = (12, B) = 48 blocks, 64 threads; bx = comp*4 + d-quarter.
// ---------------------------------------------------------------------------
__global__ void __launch_bounds__(64)
kernel_reduce() {
    const int comp = blockIdx.x >> 2;
    const int q    = blockIdx.x & 3;
    const int b    = blockIdx.y;
    const int t    = threadIdx.x;
    const int e    = q * 64 + t;

    if (blockIdx.x == 0 && t < 64) {
        int which = t >> 5;
        int lane  = t & 31;
        float v = 0.f;
#pragma unroll
        for (int i = 0; i < MSPLIT / 32; ++i)
            v += g_csp[b][lane + i * 32][which];
#pragma unroll
        for (int off = 16; off > 0; off >>= 1)
            v += __shfl_xor_sync(0xffffffffu, v, off, 32);
        if (lane == 0) g_CS[b][which] = v;
    }

    float4 acc = make_float4(0.f, 0.f, 0.f, 0.f);
#pragma unroll 8
    for (int ms = 0; ms < MSPLIT; ++ms) {
        float4 v = ((const float4*)g_part[b][ms][comp])[e];
        acc.x += v.x; acc.y += v.y; acc.z += v.z; acc.w += v.w;
    }
    ((float4*)g_H[b][comp])[e] = acc;
}

// ---------------------------------------------------------------------------
// Kernel 3: output pass — batched loads (MLP=8), FMA, streaming stores.
// grid = (NN/ROWS_PER_BLOCK, B) = 512 blocks, 256 threads.
// ---------------------------------------------------------------------------
__global__ void __launch_bounds__(256, 4)
kernel_out(const float* __restrict__ hidden,
           const float* __restrict__ phases,
           const float* __restrict__ alpha_p,
           float* __restrict__ out) {
    __shared__ float scn[ROWS_PER_BLOCK], ssn[ROWS_PER_BLOCK], scf[ROWS_PER_BLOCK];
    const int b  = blockIdx.y;
    const int n0 = blockIdx.x * ROWS_PER_BLOCK;
    const int t  = threadIdx.x;

    const float a    = fminf(fmaxf(alpha_p[0], 0.f), 1.f);
    const float beta = 1.f - a;

    if (t < ROWS_PER_BLOCK) {
        float p = phases[b * NN + n0 + t];
        float sn, cn;
        sincosf(p, &sn, &cn);
        float C = g_CS[b][0], S = g_CS[b][1];
        float den = fmaxf(0.5f * ((float)NN + fmaf(cn, C, sn * S)), EPSV);
        scn[t] = cn;
        ssn[t] = sn;
        scf[t] = a * 0.5f / den;
    }
    __syncthreads();

    const float4 H0 = ((const float4*)g_H[b][0])[t];
    const float4 Hc = ((const float4*)g_H[b][1])[t];
    const float4 Hs = ((const float4*)g_H[b][2])[t];

    const float4* hv = (const float4*)(hidden + ((size_t)b * NN + n0) * DDIM) + t;
    float4*       ov = (float4*)(out + ((size_t)b * NN + n0) * DDIM) + t;

    float4 buf[BATCH];
#pragma unroll
    for (int rr = 0; rr < ROWS_PER_BLOCK; rr += BATCH) {
#pragma unroll
        for (int i = 0; i < BATCH; ++i)
            buf[i] = hv[(size_t)(rr + i) * (DDIM / 4)];
#pragma unroll
        for (int i = 0; i < BATCH; ++i) {
            int r = rr + i;
            float cn = scn[r], sn = ssn[r], cf = scf[r];
            float4 h = buf[i];
            float4 o;
            o.x = fmaf(cf, fmaf(sn, Hs.x, fmaf(cn, Hc.x, H0.x)), beta * h.x);
            o.y = fmaf(cf, fmaf(sn, Hs.y, fmaf(cn, Hc.y, H0.y)), beta * h.y);
            o.z = fmaf(cf, fmaf(sn, Hs.z, fmaf(cn, Hc.z, H0.z)), beta * h.z);
            o.w = fmaf(cf, fmaf(sn, Hs.w, fmaf(cn, Hc.w, H0.w)), beta * h.w);
            __stcs(&ov[(size_t)r * (DDIM / 4)], o);   // evict-first: protect L2 hidden
        }
    }
}

// ---------------------------------------------------------------------------
// Launch — exactly 3 kernels.
// ---------------------------------------------------------------------------
extern "C" void kernel_launch(void* const* d_in, const int* in_sizes, int n_in,
                              void* d_out, int out_size) {
    const float* hidden = (const float*)d_in[0];
    const float* phases = (const float*)d_in[1];
    const float* alpha  = (const float*)d_in[2];
    float* out = (float*)d_out;

    const int B = in_sizes[1] / NN;

    kernel_part<<<dim3(MSPLIT, B), 256>>>(hidden, phases);
    kernel_reduce<<<dim3(12, B), 64>>>();
    kernel_out<<<dim3(NN / ROWS_PER_BLOCK, B), 256>>>(hidden, phases, alpha, out);
}

// round 11
// speedup vs baseline: 1.4984x; 1.0554x over previous
#include <cuda_runtime.h>
#include <cstdint>
#include <math.h>

#define BMAX   4
#define NN     4096
#define DDIM   1024
#define MSPLIT 256
#define MCHUNK (NN / MSPLIT)     // 16
#define EPSV   1e-6f
#define ROWS_PER_BLOCK 16
#define STAGE_ROWS 4
#define NSTAGES 2                // double buffer
#define NITER   (MCHUNK / STAGE_ROWS)          // 4 (part)
#define OITER   (ROWS_PER_BLOCK / STAGE_ROWS)  // 4 (out)

// Scratch (device globals: no allocation allowed)
__device__ float g_part[BMAX][MSPLIT][3][DDIM]; // partial H0/Hc/Hs (12 MB)
__device__ float g_csp[BMAX][MSPLIT][2];        // partial sum cos / sum sin
__device__ float g_H[BMAX][3][DDIM];            // reduced H0/Hc/Hs
__device__ float g_CS[BMAX][2];                 // final sum cos, sum sin

// ---- cp.async helpers (per-thread groups; no block sync needed) -----------
__device__ __forceinline__ void cp_async16(void* smem_dst, const void* gmem_src) {
    unsigned int s = (unsigned int)__cvta_generic_to_shared(smem_dst);
    asm volatile("cp.async.cg.shared.global [%0], [%1], 16;\n" :: "r"(s), "l"(gmem_src));
}
#define CP_COMMIT() asm volatile("cp.async.commit_group;\n" ::: "memory")
#define CP_WAIT1()  asm volatile("cp.async.wait_group 1;\n"  ::: "memory")

// ---------------------------------------------------------------------------
// Kernel 1: partial H0/Hc/Hs over 16-row m-chunks, cp.async double-buffered.
// grid = (MSPLIT, B) = 1024 blocks, 256 threads, thread owns 4 consecutive d.
// ---------------------------------------------------------------------------
__global__ void __launch_bounds__(256)
kernel_part(const float* __restrict__ hidden,
            const float* __restrict__ phases) {
    __shared__ float4 sbuf[NSTAGES][STAGE_ROWS][256];
    __shared__ float smc[MCHUNK], sms[MCHUNK];
    const int b  = blockIdx.y;
    const int ms = blockIdx.x;
    const int m0 = ms * MCHUNK;
    const int t  = threadIdx.x;

    if (t < MCHUNK) {
        float p = phases[b * NN + m0 + t];
        float s, c;
        sincosf(p, &s, &c);
        smc[t] = c;
        sms[t] = s;
        float rc = c, rs = s;
#pragma unroll
        for (int off = MCHUNK / 2; off > 0; off >>= 1) {
            rc += __shfl_xor_sync(0x0000ffffu, rc, off, 16);
            rs += __shfl_xor_sync(0x0000ffffu, rs, off, 16);
        }
        if (t == 0) { g_csp[b][ms][0] = rc; g_csp[b][ms][1] = rs; }
    }
    __syncthreads();

    const float4* hp = (const float4*)(hidden + ((size_t)b * NN + m0) * DDIM) + t;

    // prologue: stage 0
#pragma unroll
    for (int r = 0; r < STAGE_ROWS; ++r)
        cp_async16(&sbuf[0][r][t], hp + (size_t)r * (DDIM / 4));
    CP_COMMIT();

    float4 a0 = make_float4(0.f, 0.f, 0.f, 0.f);
    float4 ac = a0, as = a0;

#pragma unroll
    for (int it = 0; it < NITER; ++it) {
        int nxt = it + 1;
        if (nxt < NITER) {
#pragma unroll
            for (int r = 0; r < STAGE_ROWS; ++r)
                cp_async16(&sbuf[nxt & 1][r][t],
                           hp + (size_t)(nxt * STAGE_ROWS + r) * (DDIM / 4));
        }
        CP_COMMIT();          // uniform group count (empty on last iter)
        CP_WAIT1();           // oldest group (stage `it`) has landed
#pragma unroll
        for (int r = 0; r < STAGE_ROWS; ++r) {
            float4 h = sbuf[it & 1][r][t];
            float c = smc[it * STAGE_ROWS + r], s = sms[it * STAGE_ROWS + r];
            a0.x += h.x;               a0.y += h.y;
            a0.z += h.z;               a0.w += h.w;
            ac.x = fmaf(c, h.x, ac.x); ac.y = fmaf(c, h.y, ac.y);
            ac.z = fmaf(c, h.z, ac.z); ac.w = fmaf(c, h.w, ac.w);
            as.x = fmaf(s, h.x, as.x); as.y = fmaf(s, h.y, as.y);
            as.z = fmaf(s, h.z, as.z); as.w = fmaf(s, h.w, as.w);
        }
    }
    ((float4*)g_part[b][ms][0])[t] = a0;
    ((float4*)g_part[b][ms][1])[t] = ac;
    ((float4*)g_part[b][ms][2])[t] = as;
}

// ---------------------------------------------------------------------------
// Kernel 2: fold MSPLIT partials -> g_H with a 4-way split fold.
// grid = (12, B), 256 threads. Block: comp = bx>>2, d-quarter = bx&3 (64 f4).
// Thread t: col = q*64 + (t&63), fold slice fs = t>>6 (64 partials each).
// ---------------------------------------------------------------------------
__global__ void __launch_bounds__(256)
kernel_reduce() {
    __shared__ float4 sred[4][64];
    const int comp = blockIdx.x >> 2;
    const int q    = blockIdx.x & 3;
    const int b    = blockIdx.y;
    const int t    = threadIdx.x;
    const int col  = q * 64 + (t & 63);
    const int fs   = t >> 6;                  // 0..3

    if (blockIdx.x == 0 && t < 64) {
        int which = t >> 5;
        int lane  = t & 31;
        float v = 0.f;
#pragma unroll
        for (int i = 0; i < MSPLIT / 32; ++i)
            v += g_csp[b][lane + i * 32][which];
#pragma unroll
        for (int off = 16; off > 0; off >>= 1)
            v += __shfl_xor_sync(0xffffffffu, v, off, 32);
        if (lane == 0) g_CS[b][which] = v;
    }

    float4 acc = make_float4(0.f, 0.f, 0.f, 0.f);
    float4 buf[8];
    const int ms0 = fs * (MSPLIT / 4);
#pragma unroll
    for (int mm = 0; mm < MSPLIT / 4; mm += 8) {
#pragma unroll
        for (int i = 0; i < 8; ++i)
            buf[i] = ((const float4*)g_part[b][ms0 + mm + i][comp])[col];
#pragma unroll
        for (int i = 0; i < 8; ++i) {
            acc.x += buf[i].x; acc.y += buf[i].y;
            acc.z += buf[i].z; acc.w += buf[i].w;
        }
    }
    if (fs != 0) sred[fs][t & 63] = acc;
    __syncthreads();
    if (t < 64) {
#pragma unroll
        for (int i = 1; i < 4; ++i) {
            float4 v = sred[i][t];
            acc.x += v.x; acc.y += v.y; acc.z += v.z; acc.w += v.w;
        }
        ((float4*)g_H[b][comp])[col] = acc;
    }
}

// ---------------------------------------------------------------------------
// Kernel 3: output pass — cp.async double-buffered hidden reads (L2-hot),
// pure FMA, evict-first stores.
// grid = (NN/ROWS_PER_BLOCK, B) = 1024 blocks, 256 threads.
// ---------------------------------------------------------------------------
__global__ void __launch_bounds__(256)
kernel_out(const float* __restrict__ hidden,
           const float* __restrict__ phases,
           const float* __restrict__ alpha_p,
           float* __restrict__ out) {
    __shared__ float4 sbuf[NSTAGES][STAGE_ROWS][256];
    __shared__ float scn[ROWS_PER_BLOCK], ssn[ROWS_PER_BLOCK], scf[ROWS_PER_BLOCK];
    const int b  = blockIdx.y;
    const int n0 = blockIdx.x * ROWS_PER_BLOCK;
    const int t  = threadIdx.x;

    const float a    = fminf(fmaxf(alpha_p[0], 0.f), 1.f);
    const float beta = 1.f - a;

    if (t < ROWS_PER_BLOCK) {
        float p = phases[b * NN + n0 + t];
        float sn, cn;
        sincosf(p, &sn, &cn);
        float C = g_CS[b][0], S = g_CS[b][1];
        float den = fmaxf(0.5f * ((float)NN + fmaf(cn, C, sn * S)), EPSV);
        scn[t] = cn;
        ssn[t] = sn;
        scf[t] = a * 0.5f / den;
    }
    __syncthreads();

    const float4 H0 = ((const float4*)g_H[b][0])[t];
    const float4 Hc = ((const float4*)g_H[b][1])[t];
    const float4 Hs = ((const float4*)g_H[b][2])[t];

    const float4* hv = (const float4*)(hidden + ((size_t)b * NN + n0) * DDIM) + t;
    float4*       ov = (float4*)(out + ((size_t)b * NN + n0) * DDIM) + t;

    // prologue: stage 0
#pragma unroll
    for (int r = 0; r < STAGE_ROWS; ++r)
        cp_async16(&sbuf[0][r][t], hv + (size_t)r * (DDIM / 4));
    CP_COMMIT();

#pragma unroll
    for (int it = 0; it < OITER; ++it) {
        int nxt = it + 1;
        if (nxt < OITER) {
#pragma unroll
            for (int r = 0; r < STAGE_ROWS; ++r)
                cp_async16(&sbuf[nxt & 1][r][t],
                           hv + (size_t)(nxt * STAGE_ROWS + r) * (DDIM / 4));
        }
        CP_COMMIT();
        CP_WAIT1();
#pragma unroll
        for (int r = 0; r < STAGE_ROWS; ++r) {
            int row = it * STAGE_ROWS + r;
            float cn = scn[row], sn = ssn[row], cf = scf[row];
            float4 h = sbuf[it & 1][r][t];
            float4 o;
            o.x = fmaf(cf, fmaf(sn, Hs.x, fmaf(cn, Hc.x, H0.x)), beta * h.x);
            o.y = fmaf(cf, fmaf(sn, Hs.y, fmaf(cn, Hc.y, H0.y)), beta * h.y);
            o.z = fmaf(cf, fmaf(sn, Hs.z, fmaf(cn, Hc.z, H0.z)), beta * h.z);
            o.w = fmaf(cf, fmaf(sn, Hs.w, fmaf(cn, Hc.w, H0.w)), beta * h.w);
            __stcs(&ov[(size_t)row * (DDIM / 4)], o);  // evict-first
        }
    }
}

// ---------------------------------------------------------------------------
// Launch — exactly 3 kernels.
// ---------------------------------------------------------------------------
extern "C" void kernel_launch(void* const* d_in, const int* in_sizes, int n_in,
                              void* d_out, int out_size) {
    const float* hidden = (const float*)d_in[0];
    const float* phases = (const float*)d_in[1];
    const float* alpha  = (const float*)d_in[2];
    float* out = (float*)d_out;

    const int B = in_sizes[1] / NN;

    kernel_part<<<dim3(MSPLIT, B), 256>>>(hidden, phases);
    kernel_reduce<<<dim3(12, B), 256>>>();
    kernel_out<<<dim3(NN / ROWS_PER_BLOCK, B), 256>>>(hidden, phases, alpha, out);
}

// round 13
// speedup vs baseline: 1.6321x; 1.0892x over previous
#include <cuda_runtime.h>
#include <cstdint>
#include <math.h>

#define BMAX   4
#define NN     4096
#define DDIM   1024
#define MSPLIT 128
#define MCHUNK (NN / MSPLIT)     // 32
#define EPSV   1e-6f
#define ROWS_PER_BLOCK 32
#define STAGE_ROWS 2
#define NSTAGES 5                // 5-deep pipeline, 4 data groups in flight (40KB smem)
#define NITER   (MCHUNK / STAGE_ROWS)          // 16 (part)
#define OITER   (ROWS_PER_BLOCK / STAGE_ROWS)  // 16 (out)

// Scratch (device globals: no allocation allowed)
__device__ float g_part[BMAX][MSPLIT][3][DDIM]; // partial H0/Hc/Hs (6 MB)
__device__ float g_csp[BMAX][MSPLIT][2];        // partial sum cos / sum sin
__device__ float g_H[BMAX][3][DDIM];            // reduced H0/Hc/Hs
__device__ float g_CS[BMAX][2];                 // final sum cos, sum sin

// ---- cp.async helpers (per-thread groups; no block sync needed) -----------
__device__ __forceinline__ void cp_async16(void* smem_dst, const void* gmem_src) {
    unsigned int s = (unsigned int)__cvta_generic_to_shared(smem_dst);
    asm volatile("cp.async.cg.shared.global [%0], [%1], 16;\n" :: "r"(s), "l"(gmem_src));
}
#define CP_COMMIT() asm volatile("cp.async.commit_group;\n" ::: "memory")
#define CP_WAIT4()  asm volatile("cp.async.wait_group 4;\n" ::: "memory")

// ---------------------------------------------------------------------------
// Kernel 1: partial H0/Hc/Hs over 32-row m-chunks, 5-stage cp.async pipeline.
// grid = (MSPLIT, B) = 512 blocks (single wave), 256 threads.
// ---------------------------------------------------------------------------
__global__ void __launch_bounds__(256)
kernel_part(const float* __restrict__ hidden,
            const float* __restrict__ phases) {
    __shared__ float4 sbuf[NSTAGES][STAGE_ROWS][256];
    __shared__ float smc[MCHUNK], sms[MCHUNK];
    const int b  = blockIdx.y;
    const int ms = blockIdx.x;
    const int m0 = ms * MCHUNK;
    const int t  = threadIdx.x;

    if (t < MCHUNK) {
        float p = phases[b * NN + m0 + t];
        float s, c;
        sincosf(p, &s, &c);
        smc[t] = c;
        sms[t] = s;
        float rc = c, rs = s;
#pragma unroll
        for (int off = 16; off > 0; off >>= 1) {
            rc += __shfl_xor_sync(0xffffffffu, rc, off);
            rs += __shfl_xor_sync(0xffffffffu, rs, off);
        }
        if (t == 0) { g_csp[b][ms][0] = rc; g_csp[b][ms][1] = rs; }
    }
    __syncthreads();

    const float4* hp = (const float4*)(hidden + ((size_t)b * NN + m0) * DDIM) + t;

    // prologue: stages 0..NSTAGES-2, one commit group each
#pragma unroll
    for (int s = 0; s < NSTAGES - 1; ++s) {
#pragma unroll
        for (int r = 0; r < STAGE_ROWS; ++r)
            cp_async16(&sbuf[s][r][t], hp + (size_t)(s * STAGE_ROWS + r) * (DDIM / 4));
        CP_COMMIT();
    }

    float4 a0 = make_float4(0.f, 0.f, 0.f, 0.f);
    float4 ac = a0, as = a0;

#pragma unroll
    for (int it = 0; it < NITER; ++it) {
        const int nxt = it + NSTAGES - 1;
        if (nxt < NITER) {
#pragma unroll
            for (int r = 0; r < STAGE_ROWS; ++r)
                cp_async16(&sbuf[nxt % NSTAGES][r][t],
                           hp + (size_t)(nxt * STAGE_ROWS + r) * (DDIM / 4));
        }
        CP_COMMIT();          // uniform group count (empty near the end)
        CP_WAIT4();           // group `it` (stage it) has landed
#pragma unroll
        for (int r = 0; r < STAGE_ROWS; ++r) {
            float4 h = sbuf[it % NSTAGES][r][t];
            float c = smc[it * STAGE_ROWS + r], s = sms[it * STAGE_ROWS + r];
            a0.x += h.x;               a0.y += h.y;
            a0.z += h.z;               a0.w += h.w;
            ac.x = fmaf(c, h.x, ac.x); ac.y = fmaf(c, h.y, ac.y);
            ac.z = fmaf(c, h.z, ac.z); ac.w = fmaf(c, h.w, ac.w);
            as.x = fmaf(s, h.x, as.x); as.y = fmaf(s, h.y, as.y);
            as.z = fmaf(s, h.z, as.z); as.w = fmaf(s, h.w, as.w);
        }
    }
    ((float4*)g_part[b][ms][0])[t] = a0;
    ((float4*)g_part[b][ms][1])[t] = ac;
    ((float4*)g_part[b][ms][2])[t] = as;
}

// ---------------------------------------------------------------------------
// Kernel 2: fold MSPLIT partials -> g_H with a 4-way split fold.
// grid = (12, B), 256 threads. Block: comp = bx>>2, d-quarter = bx&3 (64 f4).
// ---------------------------------------------------------------------------
__global__ void __launch_bounds__(256)
kernel_reduce() {
    __shared__ float4 sred[4][64];
    const int comp = blockIdx.x >> 2;
    const int q    = blockIdx.x & 3;
    const int b    = blockIdx.y;
    const int t    = threadIdx.x;
    const int col  = q * 64 + (t & 63);
    const int fs   = t >> 6;                  // 0..3

    if (blockIdx.x == 0 && t < 64) {
        int which = t >> 5;
        int lane  = t & 31;
        float v = 0.f;
#pragma unroll
        for (int i = 0; i < MSPLIT / 32; ++i)
            v += g_csp[b][lane + i * 32][which];
#pragma unroll
        for (int off = 16; off > 0; off >>= 1)
            v += __shfl_xor_sync(0xffffffffu, v, off, 32);
        if (lane == 0) g_CS[b][which] = v;
    }

    float4 acc = make_float4(0.f, 0.f, 0.f, 0.f);
    float4 buf[8];
    const int ms0 = fs * (MSPLIT / 4);
#pragma unroll
    for (int mm = 0; mm < MSPLIT / 4; mm += 8) {
#pragma unroll
        for (int i = 0; i < 8; ++i)
            buf[i] = ((const float4*)g_part[b][ms0 + mm + i][comp])[col];
#pragma unroll
        for (int i = 0; i < 8; ++i) {
            acc.x += buf[i].x; acc.y += buf[i].y;
            acc.z += buf[i].z; acc.w += buf[i].w;
        }
    }
    if (fs != 0) sred[fs][t & 63] = acc;
    __syncthreads();
    if (t < 64) {
#pragma unroll
        for (int i = 1; i < 4; ++i) {
            float4 v = sred[i][t];
            acc.x += v.x; acc.y += v.y; acc.z += v.z; acc.w += v.w;
        }
        ((float4*)g_H[b][comp])[col] = acc;
    }
}

// ---------------------------------------------------------------------------
// Kernel 3: output pass — 5-stage cp.async pipeline, FMA, evict-first stores.
// grid = (NN/ROWS_PER_BLOCK, B) = 512 blocks (single wave), 256 threads.
// ---------------------------------------------------------------------------
__global__ void __launch_bounds__(256)
kernel_out(const float* __restrict__ hidden,
           const float* __restrict__ phases,
           const float* __restrict__ alpha_p,
           float* __restrict__ out) {
    __shared__ float4 sbuf[NSTAGES][STAGE_ROWS][256];
    __shared__ float scn[ROWS_PER_BLOCK], ssn[ROWS_PER_BLOCK], scf[ROWS_PER_BLOCK];
    const int b  = blockIdx.y;
    const int n0 = blockIdx.x * ROWS_PER_BLOCK;
    const int t  = threadIdx.x;

    const float a    = fminf(fmaxf(alpha_p[0], 0.f), 1.f);
    const float beta = 1.f - a;

    if (t < ROWS_PER_BLOCK) {
        float p = phases[b * NN + n0 + t];
        float sn, cn;
        sincosf(p, &sn, &cn);
        float C = g_CS[b][0], S = g_CS[b][1];
        float den = fmaxf(0.5f * ((float)NN + fmaf(cn, C, sn * S)), EPSV);
        scn[t] = cn;
        ssn[t] = sn;
        scf[t] = a * 0.5f / den;
    }
    __syncthreads();

    const float4 H0 = ((const float4*)g_H[b][0])[t];
    const float4 Hc = ((const float4*)g_H[b][1])[t];
    const float4 Hs = ((const float4*)g_H[b][2])[t];

    const float4* hv = (const float4*)(hidden + ((size_t)b * NN + n0) * DDIM) + t;
    float4*       ov = (float4*)(out + ((size_t)b * NN + n0) * DDIM) + t;

    // prologue: stages 0..NSTAGES-2
#pragma unroll
    for (int s = 0; s < NSTAGES - 1; ++s) {
#pragma unroll
        for (int r = 0; r < STAGE_ROWS; ++r)
            cp_async16(&sbuf[s][r][t], hv + (size_t)(s * STAGE_ROWS + r) * (DDIM / 4));
        CP_COMMIT();
    }

#pragma unroll
    for (int it = 0; it < OITER; ++it) {
        const int nxt = it + NSTAGES - 1;
        if (nxt < OITER) {
#pragma unroll
            for (int r = 0; r < STAGE_ROWS; ++r)
                cp_async16(&sbuf[nxt % NSTAGES][r][t],
                           hv + (size_t)(nxt * STAGE_ROWS + r) * (DDIM / 4));
        }
        CP_COMMIT();
        CP_WAIT4();
#pragma unroll
        for (int r = 0; r < STAGE_ROWS; ++r) {
            int row = it * STAGE_ROWS + r;
            float cn = scn[row], sn = ssn[row], cf = scf[row];
            float4 h = sbuf[it % NSTAGES][r][t];
            float4 o;
            o.x = fmaf(cf, fmaf(sn, Hs.x, fmaf(cn, Hc.x, H0.x)), beta * h.x);
            o.y = fmaf(cf, fmaf(sn, Hs.y, fmaf(cn, Hc.y, H0.y)), beta * h.y);
            o.z = fmaf(cf, fmaf(sn, Hs.z, fmaf(cn, Hc.z, H0.z)), beta * h.z);
            o.w = fmaf(cf, fmaf(sn, Hs.w, fmaf(cn, Hc.w, H0.w)), beta * h.w);
            __stcs(&ov[(size_t)row * (DDIM / 4)], o);  // evict-first
        }
    }
}

// ---------------------------------------------------------------------------
// Launch — exactly 3 kernels.
// ---------------------------------------------------------------------------
extern "C" void kernel_launch(void* const* d_in, const int* in_sizes, int n_in,
                              void* d_out, int out_size) {
    const float* hidden = (const float*)d_in[0];
    const float* phases = (const float*)d_in[1];
    const float* alpha  = (const float*)d_in[2];
    float* out = (float*)d_out;

    const int B = in_sizes[1] / NN;

    kernel_part<<<dim3(MSPLIT, B), 256>>>(hidden, phases);
    kernel_reduce<<<dim3(12, B), 256>>>();
    kernel_out<<<dim3(NN / ROWS_PER_BLOCK, B), 256>>>(hidden, phases, alpha, out);
}